// round 11
// baseline (speedup 1.0000x reference)
#include <cuda_runtime.h>
#include <cstdint>

// Q = L @ L^T, L lower-triangular 3x3 from packed [a,b,c,d,e,f]:
//   Q00=a*a  Q01=a*b      Q02=a*d
//   Q10=a*b  Q11=b*b+c*c  Q12=b*d+c*e
//   Q20=a*d  Q21=b*d+c*e  Q22=d*d+e*e+f*f
//
// FULLY BULK pipeline: 3 tiles/block.
// Reads:  3 x 6144B cp.async.bulk (TMA-1D) gmem->smem, one mbarrier each,
//         issued up-front by one elected thread; warps compute tile i as
//         soon as mbar[i] flips.
// Writes: one 27KB cp.async.bulk smem->gmem (the R9/R10 winning lever).
// Both directions now present DRAM with large strictly-sequential bursts,
// minimizing R/W turnarounds; SM issue work is near zero.

#define TPB 128
#define ROWS_PB 256
#define TILES_PB 3
#define TILE_IN_BYTES (ROWS_PB * 6 * 4)   // 6144 B
#define TILE_IN_FLOATS (ROWS_PB * 6)
#define TILE_OUT_FLOATS (ROWS_PB * 9)     // 9216 B
#define W_ROWS 64
#define W_OUT_FLOATS (W_ROWS * 9)

// ---- bulk copy / mbarrier PTX ----
__device__ __forceinline__ void mbar_init(uint32_t addr, uint32_t count) {
    asm volatile("mbarrier.init.shared.b64 [%0], %1;\n" :: "r"(addr), "r"(count) : "memory");
}
__device__ __forceinline__ void mbar_expect_tx(uint32_t addr, uint32_t bytes) {
    asm volatile("mbarrier.arrive.expect_tx.shared.b64 _, [%0], %1;\n"
                 :: "r"(addr), "r"(bytes) : "memory");
}
__device__ __forceinline__ void mbar_wait0(uint32_t addr) {
    uint32_t done = 0;
    while (!done) {
        asm volatile(
            "{\n\t.reg .pred p;\n\t"
            "mbarrier.try_wait.parity.acquire.cta.shared::cta.b64 p, [%1], 0, 0x989680;\n\t"
            "selp.b32 %0, 1, 0, p;\n\t}"
            : "=r"(done) : "r"(addr) : "memory");
    }
}
__device__ __forceinline__ void bulk_load(uint32_t saddr, const void* gaddr,
                                          uint32_t bytes, uint32_t mbar) {
    asm volatile(
        "cp.async.bulk.shared::cta.global.mbarrier::complete_tx::bytes [%0], [%1], %2, [%3];\n"
        :: "r"(saddr), "l"(gaddr), "r"(bytes), "r"(mbar) : "memory");
}
__device__ __forceinline__ void bulk_store(void* gaddr, uint32_t saddr, uint32_t bytes) {
    asm volatile("cp.async.bulk.global.shared::cta.bulk_group [%0], [%1], %2;\n"
                 :: "l"(gaddr), "r"(saddr), "r"(bytes) : "memory");
}
__device__ __forceinline__ void bulk_commit() {
    asm volatile("cp.async.bulk.commit_group;\n" ::: "memory");
}
template <int N>
__device__ __forceinline__ void bulk_wait() {
    asm volatile("cp.async.bulk.wait_group %0;\n" :: "n"(N) : "memory");
}
__device__ __forceinline__ void fence_async_shared() {
    asm volatile("fence.proxy.async.shared::cta;\n" ::: "memory");
}

__device__ __forceinline__ void row_to_q(const float* __restrict__ v, float* __restrict__ o) {
    const float a = v[0], b = v[1], c = v[2], d = v[3], e = v[4], f = v[5];
    const float ab = a * b;
    const float ad = a * d;
    const float bdce = fmaf(b, d, c * e);
    o[0] = a * a;
    o[1] = ab;
    o[2] = ad;
    o[3] = ab;
    o[4] = fmaf(b, b, c * c);
    o[5] = bdce;
    o[6] = ad;
    o[7] = bdce;
    o[8] = fmaf(d, d, fmaf(e, e, f * f));
}

// Compute this warp's 64 rows of one tile: smem input slice -> smem output slice.
__device__ __forceinline__ void warp_compute(const float* __restrict__ sin_w,
                                             float* __restrict__ sout_w, int l)
{
#pragma unroll
    for (int j = 0; j < 2; j++) {
        const int r = l + 32 * j;
        float v[6], o[9];
#pragma unroll
        for (int k = 0; k < 6; k++) v[k] = sin_w[r * 6 + k];
        row_to_q(v, o);
#pragma unroll
        for (int k = 0; k < 9; k++) sout_w[r * 9 + k] = o[k];
    }
}

__global__ __launch_bounds__(TPB) void chol_to_cov_fullbulk(const float* __restrict__ in,
                                                            float* __restrict__ out,
                                                            int num_tiles)
{
    __shared__ alignas(16) float s_in[TILES_PB * TILE_IN_FLOATS];    // 18 KB
    __shared__ alignas(16) float s_out[TILES_PB * TILE_OUT_FLOATS];  // 27 KB
    __shared__ alignas(8) unsigned long long mbar[TILES_PB];

    const int t = threadIdx.x;
    const int w = t >> 5;
    const int l = t & 31;

    const int tile0 = blockIdx.x * TILES_PB;
    const int nt = (num_tiles - tile0 < TILES_PB) ? (num_tiles - tile0) : TILES_PB;

    // Init mbarriers, then issue the bulk loads (one 6144B op per tile).
    if (t == 0) {
#pragma unroll
        for (int i = 0; i < TILES_PB; i++) mbar_init((uint32_t)__cvta_generic_to_shared(&mbar[i]), 1);
        // fence so the async proxy sees initialized barriers before complete_tx
        fence_async_shared();
#pragma unroll
        for (int i = 0; i < TILES_PB; i++) {
            if (i < nt) {
                const uint32_t mb = (uint32_t)__cvta_generic_to_shared(&mbar[i]);
                mbar_expect_tx(mb, TILE_IN_BYTES);
                bulk_load((uint32_t)__cvta_generic_to_shared(&s_in[i * TILE_IN_FLOATS]),
                          in + (size_t)(tile0 + i) * TILE_IN_FLOATS,
                          TILE_IN_BYTES, mb);
            }
        }
    }
    __syncthreads();   // mbar init visible to all waiting threads

#pragma unroll
    for (int i = 0; i < TILES_PB; i++) {
        if (i < nt) {
            mbar_wait0((uint32_t)__cvta_generic_to_shared(&mbar[i]));
            warp_compute(&s_in[i * TILE_IN_FLOATS + w * W_ROWS * 6],
                         &s_out[i * TILE_OUT_FLOATS + w * W_OUT_FLOATS], l);
        }
    }

    // One large sequential bulk store for the whole block output.
    fence_async_shared();
    __syncthreads();
    if (t == 0) {
        bulk_store(out + (size_t)tile0 * TILE_OUT_FLOATS,
                   (uint32_t)__cvta_generic_to_shared(&s_out[0]),
                   (uint32_t)nt * TILE_OUT_FLOATS * 4u);
        bulk_commit();
        bulk_wait<0>();  // keep smem alive until the bulk engine has read it
    }
}

// Scalar tail for the (< ROWS_PB) remainder rows.
__global__ void chol_to_cov_tail(const float* __restrict__ in,
                                 float* __restrict__ out,
                                 int start_row, int n_rows)
{
    const int r = start_row + blockIdx.x * blockDim.x + threadIdx.x;
    if (r >= n_rows) return;
    float v[6], o[9];
#pragma unroll
    for (int k = 0; k < 6; k++) v[k] = in[(size_t)r * 6 + k];
    row_to_q(v, o);
#pragma unroll
    for (int k = 0; k < 9; k++) out[(size_t)r * 9 + k] = o[k];
}

extern "C" void kernel_launch(void* const* d_in, const int* in_sizes, int n_in,
                              void* d_out, int out_size)
{
    const float* in = (const float*)d_in[0];
    float* out = (float*)d_out;
    const int n_rows = in_sizes[0] / 6;

    const int num_tiles = n_rows / ROWS_PB;
    if (num_tiles > 0) {
        const int blocks = (num_tiles + TILES_PB - 1) / TILES_PB;
        chol_to_cov_fullbulk<<<blocks, TPB>>>(in, out, num_tiles);
    }
    const int done = num_tiles * ROWS_PB;
    if (done < n_rows) {
        const int rem = n_rows - done;
        chol_to_cov_tail<<<(rem + 127) / 128, 128>>>(in, out, done, n_rows);
    }
}